// round 15
// baseline (speedup 1.0000x reference)
#include <cuda_runtime.h>
#include <cuda_bf16.h>
#include <cstdint>
#include <math.h>

#define HIDDEN 1024
#define KDIM 64
#define BATCH 4
#define SQDIM 4096
#define SKDIM 4096
#define NSPLIT 8
#define SPLIT_S (SKDIM / NSPLIT)   // 512

// ---------------- device scratch (no allocation allowed) --------------------
__device__ __nv_bfloat16 g_qh[BATCH * SQDIM * KDIM];
__device__ __nv_bfloat16 g_ql[BATCH * SQDIM * KDIM];
__device__ __nv_bfloat16 g_kh[BATCH * SKDIM * KDIM];
__device__ __nv_bfloat16 g_kl[BATCH * SKDIM * KDIM];
__device__ __nv_bfloat16 g_vth[BATCH * KDIM * SKDIM];  // V^T: [b][j][s]
__device__ __nv_bfloat16 g_vtl[BATCH * KDIM * SKDIM];
__device__ __nv_bfloat16 g_och[BATCH * SQDIM * KDIM];
__device__ __nv_bfloat16 g_ocl[BATCH * SQDIM * KDIM];
__device__ __nv_bfloat16 g_sh[(size_t)BATCH * SQDIM * SKDIM];  // raw scores hi
__device__ __nv_bfloat16 g_sl[(size_t)BATCH * SQDIM * SKDIM];  // raw scores lo
__device__ float  g_opart[(size_t)NSPLIT * BATCH * SQDIM * KDIM];
__device__ float2 g_part[(size_t)BATCH * SQDIM * 64];
__device__ float2 g_rows[BATCH * SQDIM];

// ---------------- helpers ---------------------------------------------------
__device__ __forceinline__ uint32_t smem_u32(const void* p) {
    uint32_t a;
    asm("{ .reg .u64 t; cvta.to.shared.u64 t, %1; cvt.u32.u64 %0, t; }"
        : "=r"(a) : "l"(p));
    return a;
}
__device__ __forceinline__ uint32_t sw128(uint32_t x) { return x ^ ((x >> 3) & 0x70); }

__device__ __forceinline__ void ldm_x4(uint32_t* r, uint32_t addr) {
    asm volatile("ldmatrix.sync.aligned.m8n8.x4.shared.b16 {%0,%1,%2,%3}, [%4];"
                 : "=r"(r[0]), "=r"(r[1]), "=r"(r[2]), "=r"(r[3]) : "r"(addr));
}
__device__ __forceinline__ void mma_bf16(float* d, const uint32_t* a, const uint32_t* b) {
    asm volatile(
        "mma.sync.aligned.m16n8k16.row.col.f32.bf16.bf16.f32 "
        "{%0,%1,%2,%3}, {%4,%5,%6,%7}, {%8,%9}, {%0,%1,%2,%3};"
        : "+f"(d[0]), "+f"(d[1]), "+f"(d[2]), "+f"(d[3])
        : "r"(a[0]), "r"(a[1]), "r"(a[2]), "r"(a[3]), "r"(b[0]), "r"(b[1]));
}
__device__ __forceinline__ uint32_t pack_bf(__nv_bfloat16 a, __nv_bfloat16 b) {
    return ((uint32_t)__bfloat16_as_ushort(b) << 16) | __bfloat16_as_ushort(a);
}
__device__ __forceinline__ void split2(float x, float y, uint32_t& hi, uint32_t& lo) {
    __nv_bfloat16 hx = __float2bfloat16(x), hy = __float2bfloat16(y);
    __nv_bfloat16 lx = __float2bfloat16(x - __bfloat162float(hx));
    __nv_bfloat16 ly = __float2bfloat16(y - __bfloat162float(hy));
    hi = pack_bf(hx, hy);
    lo = pack_bf(lx, ly);
}
__device__ __forceinline__ void l2_prefetch(const void* p) {
    asm volatile("prefetch.global.L2 [%0];" :: "l"(p));
}
__device__ __forceinline__ void cp_async16(uint32_t smem_addr, const void* gptr) {
    asm volatile("cp.async.cg.shared.global [%0], [%1], 16;"
                 :: "r"(smem_addr), "l"(gptr) : "memory");
}
__device__ __forceinline__ void cp_commit() {
    asm volatile("cp.async.commit_group;" ::: "memory");
}
__device__ __forceinline__ void cp_wait0() {
    asm volatile("cp.async.wait_group 0;" ::: "memory");
}
// A-fragment ldmatrix address (16x16 tile in a [rows][64bf16] sw128 tile)
__device__ __forceinline__ uint32_t a_addr(int row0, int ks, int lane) {
    int r = row0 + (lane & 15);
    int off = ks * 32 + ((lane >> 4) << 4);
    return sw128((uint32_t)r * 128 + off);
}
// B-pair fragment (two n-tiles of 8): rows are n (or s) of an n×k layout
__device__ __forceinline__ uint32_t b_addr(int row0, int ks, int lane) {
    int r = row0 + ((lane >> 4) << 3) + (lane & 7);
    int off = ks * 32 + (((lane >> 3) & 1) << 4);
    return sw128((uint32_t)r * 128 + off);
}

// ---------------------------------------------------------------------------
// Projection x3 merged (mma.sync): out = (x - mean) @ W^T -> bf16 hi/lo
// gridDim = (Mrows/64, 3): y selects q/k/v. v output is transposed.
// ---------------------------------------------------------------------------
__global__ __launch_bounds__(256) void proj3_mma(
    const float* __restrict__ xq, const float* __restrict__ xk,
    const float* __restrict__ xv,
    const float* __restrict__ Wq, const float* __restrict__ Wk,
    const float* __restrict__ Wv,
    const float* __restrict__ mq, const float* __restrict__ mk,
    const float* __restrict__ mv,
    __nv_bfloat16* __restrict__ qh, __nv_bfloat16* __restrict__ ql,
    __nv_bfloat16* __restrict__ kh, __nv_bfloat16* __restrict__ kl,
    __nv_bfloat16* __restrict__ vth, __nv_bfloat16* __restrict__ vtl)
{
    extern __shared__ char smem[];
    const uint32_t sb = smem_u32(smem);
    const uint32_t AH = 0, AL = 8192, BH = 16384, BL = 24576;
    const int tid = threadIdx.x, wid = tid >> 5, lane = tid & 31;
    const int m0 = blockIdx.x * 64;
    const int sel = blockIdx.y;

    const float* x    = sel == 0 ? xq : (sel == 1 ? xk : xv);
    const float* W    = sel == 0 ? Wq : (sel == 1 ? Wk : Wv);
    const float* mean = sel == 0 ? mq : (sel == 1 ? mk : mv);
    __nv_bfloat16* outh = sel == 0 ? qh : (sel == 1 ? kh : vth);
    __nv_bfloat16* outl = sel == 0 ? ql : (sel == 1 ? kl : vtl);
    const bool trans = (sel == 2);

    const int wm = wid >> 1, wn = wid & 1;
    const int mrow0 = wm * 16, ncol0 = wn * 32;
    float acc[4][4] = {};

    for (int k0 = 0; k0 < HIDDEN; k0 += 64) {
        #pragma unroll
        for (int i = tid; i < 1024; i += 256) {
            int r = i >> 4, c4 = i & 15;
            float4 xv4 = *(const float4*)&x[(size_t)(m0 + r) * HIDDEN + k0 + c4 * 4];
            float4 mn = *(const float4*)&mean[k0 + c4 * 4];
            uint32_t h0, l0, h1, l1;
            split2(xv4.x - mn.x, xv4.y - mn.y, h0, l0);
            split2(xv4.z - mn.z, xv4.w - mn.w, h1, l1);
            uint32_t so = sw128((uint32_t)r * 128 + c4 * 8);
            *(uint2*)(smem + AH + so) = make_uint2(h0, h1);
            *(uint2*)(smem + AL + so) = make_uint2(l0, l1);
        }
        #pragma unroll
        for (int i = tid; i < 1024; i += 256) {
            int r = i >> 4, c4 = i & 15;
            float4 wv = *(const float4*)&W[(size_t)r * HIDDEN + k0 + c4 * 4];
            uint32_t h0, l0, h1, l1;
            split2(wv.x, wv.y, h0, l0);
            split2(wv.z, wv.w, h1, l1);
            uint32_t so = sw128((uint32_t)r * 128 + c4 * 8);
            *(uint2*)(smem + BH + so) = make_uint2(h0, h1);
            *(uint2*)(smem + BL + so) = make_uint2(l0, l1);
        }
        __syncthreads();

        #pragma unroll
        for (int ks = 0; ks < 4; ks++) {
            uint32_t ah[4], al[4];
            uint32_t aa = a_addr(mrow0, ks, lane);
            ldm_x4(ah, sb + AH + aa);
            ldm_x4(al, sb + AL + aa);
            #pragma unroll
            for (int ntp = 0; ntp < 2; ntp++) {
                uint32_t bh[4], bl[4];
                uint32_t ba = b_addr(ncol0 + ntp * 16, ks, lane);
                ldm_x4(bh, sb + BH + ba);
                ldm_x4(bl, sb + BL + ba);
                mma_bf16(acc[ntp * 2 + 0], ah, &bh[0]);
                mma_bf16(acc[ntp * 2 + 0], al, &bh[0]);
                mma_bf16(acc[ntp * 2 + 0], ah, &bl[0]);
                mma_bf16(acc[ntp * 2 + 1], ah, &bh[2]);
                mma_bf16(acc[ntp * 2 + 1], al, &bh[2]);
                mma_bf16(acc[ntp * 2 + 1], ah, &bl[2]);
            }
        }
        __syncthreads();
    }

    #pragma unroll
    for (int nt = 0; nt < 4; nt++) {
        #pragma unroll
        for (int rh = 0; rh < 2; rh++) {
            int m = m0 + mrow0 + (lane >> 2) + rh * 8;
            int c = ncol0 + nt * 8 + (lane & 3) * 2;
            uint32_t hi, lo;
            split2(acc[nt][rh * 2 + 0], acc[nt][rh * 2 + 1], hi, lo);
            if (trans) {
                int b = m >> 12, s = m & 4095;
                size_t i0 = (size_t)b * KDIM * SKDIM + (size_t)c * SKDIM + s;
                size_t i1 = i0 + SKDIM;
                outh[i0] = __ushort_as_bfloat16((uint16_t)(hi & 0xffff));
                outh[i1] = __ushort_as_bfloat16((uint16_t)(hi >> 16));
                outl[i0] = __ushort_as_bfloat16((uint16_t)(lo & 0xffff));
                outl[i1] = __ushort_as_bfloat16((uint16_t)(lo >> 16));
            } else {
                *(uint32_t*)&outh[(size_t)m * KDIM + c] = hi;
                *(uint32_t*)&outl[(size_t)m * KDIM + c] = lo;
            }
        }
    }
}

// ---------------------------------------------------------------------------
// Pass 1: scores MMA -> raw scaled scores as bf16 hi/lo + softmax partials
// CTA tile 128q x 128s, 8 warps (4m x 2n), warp tile 32x64.
// ---------------------------------------------------------------------------
__global__ __launch_bounds__(256) void scores_mma(
    const __nv_bfloat16* __restrict__ qh, const __nv_bfloat16* __restrict__ ql,
    const __nv_bfloat16* __restrict__ kh, const __nv_bfloat16* __restrict__ kl,
    __nv_bfloat16* __restrict__ sh, __nv_bfloat16* __restrict__ sl,
    float2* __restrict__ part)
{
    extern __shared__ char smem[];
    const uint32_t sb = smem_u32(smem);
    const uint32_t QH = 0, QL = 16384, KH = 32768, KL = 49152;
    const int tid = threadIdx.x, wid = tid >> 5, lane = tid & 31;
    const int b = blockIdx.z, q0 = blockIdx.y * 128, s0 = blockIdx.x * 128;

    const size_t qoff = ((size_t)b * SQDIM + q0) * KDIM;
    const size_t koff = ((size_t)b * SKDIM + s0) * KDIM;
    #pragma unroll
    for (int i = tid; i < 1024; i += 256) {
        int r = i >> 3, c = i & 7;
        uint32_t so = sw128((uint32_t)r * 128 + c * 16);
        *(uint4*)(smem + QH + so) = *(const uint4*)&qh[qoff + (size_t)r * KDIM + c * 8];
        *(uint4*)(smem + QL + so) = *(const uint4*)&ql[qoff + (size_t)r * KDIM + c * 8];
        *(uint4*)(smem + KH + so) = *(const uint4*)&kh[koff + (size_t)r * KDIM + c * 8];
        *(uint4*)(smem + KL + so) = *(const uint4*)&kl[koff + (size_t)r * KDIM + c * 8];
    }
    __syncthreads();

    const int wm = wid >> 1, wn = wid & 1;
    const int mrow0 = wm * 32, ncol0 = wn * 64;
    float acc[2][8][4] = {};

    #pragma unroll
    for (int ks = 0; ks < 4; ks++) {
        uint32_t ah[2][4], al[2][4];
        #pragma unroll
        for (int mt = 0; mt < 2; mt++) {
            uint32_t aa = a_addr(mrow0 + mt * 16, ks, lane);
            ldm_x4(ah[mt], sb + QH + aa);
            ldm_x4(al[mt], sb + QL + aa);
        }
        #pragma unroll
        for (int ntp = 0; ntp < 4; ntp++) {
            uint32_t bh[4], bl[4];
            uint32_t ba = b_addr(ncol0 + ntp * 16, ks, lane);
            ldm_x4(bh, sb + KH + ba);
            ldm_x4(bl, sb + KL + ba);
            #pragma unroll
            for (int mt = 0; mt < 2; mt++) {
                mma_bf16(acc[mt][ntp * 2 + 0], ah[mt], &bh[0]);
                mma_bf16(acc[mt][ntp * 2 + 0], al[mt], &bh[0]);
                mma_bf16(acc[mt][ntp * 2 + 0], ah[mt], &bl[0]);
                mma_bf16(acc[mt][ntp * 2 + 1], ah[mt], &bh[2]);
                mma_bf16(acc[mt][ntp * 2 + 1], al[mt], &bh[2]);
                mma_bf16(acc[mt][ntp * 2 + 1], ah[mt], &bl[2]);
            }
        }
    }

    const int stile = blockIdx.x * 2 + wn;
    #pragma unroll
    for (int mt = 0; mt < 2; mt++) {
        #pragma unroll
        for (int rh = 0; rh < 2; rh++) {
            int qrow = q0 + mrow0 + mt * 16 + (lane >> 2) + rh * 8;
            size_t rowoff = ((size_t)b * SQDIM + qrow) * SKDIM + s0 + ncol0;
            float v[16];
            float m = -3.4e38f;
            #pragma unroll
            for (int nt = 0; nt < 8; nt++) {
                v[nt * 2 + 0] = acc[mt][nt][rh * 2 + 0] * 0.125f;
                v[nt * 2 + 1] = acc[mt][nt][rh * 2 + 1] * 0.125f;
                m = fmaxf(m, fmaxf(v[nt * 2], v[nt * 2 + 1]));
                uint32_t hi, lo;
                split2(v[nt * 2], v[nt * 2 + 1], hi, lo);
                size_t idx = rowoff + nt * 8 + (lane & 3) * 2;
                *(uint32_t*)&sh[idx] = hi;
                *(uint32_t*)&sl[idx] = lo;
            }
            m = fmaxf(m, __shfl_xor_sync(0xffffffffu, m, 1));
            m = fmaxf(m, __shfl_xor_sync(0xffffffffu, m, 2));
            float s = 0.f;
            #pragma unroll
            for (int c = 0; c < 16; c++) s += __expf(v[c] - m);
            s += __shfl_xor_sync(0xffffffffu, s, 1);
            s += __shfl_xor_sync(0xffffffffu, s, 2);
            if ((lane & 3) == 0)
                part[((size_t)b * SQDIM + qrow) * 64 + stile] = make_float2(m, s);
        }
    }
}

// ---------------------------------------------------------------------------
// Combine 64 per-tile partials -> per-row (max, 1/sum). Warp per row.
// ---------------------------------------------------------------------------
__global__ __launch_bounds__(256) void rowstats_kernel(
    const float2* __restrict__ part, float2* __restrict__ rows)
{
    const int row = blockIdx.x * 8 + (threadIdx.x >> 5);
    const int lane = threadIdx.x & 31;
    float2 p0 = part[(size_t)row * 64 + lane];
    float2 p1 = part[(size_t)row * 64 + 32 + lane];
    float m = fmaxf(p0.x, p1.x);
    float s = p0.y * __expf(p0.x - m) + p1.y * __expf(p1.x - m);
    #pragma unroll
    for (int o = 16; o; o >>= 1) {
        float om = __shfl_xor_sync(0xffffffffu, m, o);
        float os = __shfl_xor_sync(0xffffffffu, s, o);
        float nm = fmaxf(m, om);
        s = s * __expf(m - nm) + os * __expf(om - nm);
        m = nm;
    }
    if (lane == 0) rows[row] = make_float2(m, 1.0f / s);
}

// ---------------------------------------------------------------------------
// Pass 2: read bf16 hi/lo raw scores, normalize -> write final f32 attn,
// then p@V^T into split-K partials. CTA = 64q x 512s-split, 256 threads.
// V staged via cp.async; L2 prefetch of next score tile.
// smem: P0H 0 | P0L 8K | P1H 16K | P1L 24K | V0H 32K | V0L 40K |
//       V1H 48K | V1L 56K | RS 64K  (total ~64.5K)
// ---------------------------------------------------------------------------
__global__ __launch_bounds__(256) void av2_mma(
    const __nv_bfloat16* __restrict__ sh, const __nv_bfloat16* __restrict__ sl,
    float* __restrict__ attn,
    const __nv_bfloat16* __restrict__ vth, const __nv_bfloat16* __restrict__ vtl,
    const float2* __restrict__ rows, float* __restrict__ opart)
{
    extern __shared__ char smem[];
    const uint32_t sb = smem_u32(smem);
    const uint32_t P0H = 0, P0L = 8192, P1H = 16384, P1L = 24576;
    const uint32_t V0H = 32768, V0L = 40960, V1H = 49152, V1L = 57344;
    const uint32_t RS = 65536;
    const int tid = threadIdx.x, wid = tid >> 5, lane = tid & 31;
    const int qt = blockIdx.x, sp = blockIdx.y, b = blockIdx.z;
    const int q0 = qt * 64;

    if (tid < 64)
        *(float2*)(smem + RS + tid * 8) = rows[(size_t)b * SQDIM + q0 + tid];

    const __nv_bfloat16* vhb = vth + (size_t)b * KDIM * SKDIM;
    const __nv_bfloat16* vlb = vtl + (size_t)b * KDIM * SKDIM;
    const size_t rowbase = ((size_t)b * SQDIM + q0) * SKDIM;
    const __nv_bfloat16* shb = sh + rowbase;
    const __nv_bfloat16* slb = sl + rowbase;
    float* attnb = attn + rowbase;

    // normalize-loop addressing: 64 rows x 128 cols, 8x4 cols per thread
    const int lrow = tid >> 5;           // 0..7
    const int lcol = lane * 4;           // 0..124
    const int halfsel = lcol >> 6;       // 0 or 1
    const int ch = lcol & 63;
    const uint32_t PHb = halfsel ? P1H : P0H;
    const uint32_t PLb = halfsel ? P1L : P0L;

    const int wm = wid >> 1, wn = wid & 1;
    const int mrow0 = wm * 16, ncol0 = wn * 32;
    float acc_av[4][4] = {};

    __syncthreads();  // RS visible

    for (int st = 0; st < SPLIT_S / 128; st++) {
        const int s0 = sp * SPLIT_S + st * 128;

        // V tiles via cp.async (overlap with normalize phase below)
        #pragma unroll
        for (int i = tid; i < 512; i += 256) {
            int j = i >> 3, c = i & 7;
            uint32_t so = sw128((uint32_t)j * 128 + c * 16);
            const size_t g0 = (size_t)j * SKDIM + s0 + c * 8;
            cp_async16(sb + V0H + so, &vhb[g0]);
            cp_async16(sb + V0L + so, &vlb[g0]);
            cp_async16(sb + V1H + so, &vhb[g0 + 64]);
            cp_async16(sb + V1L + so, &vlb[g0 + 64]);
        }
        cp_commit();

        // normalize: read bf16 hi/lo scores, p = exp(x-m)*inv, write f32 attn,
        // stage P (bf16 hi/lo of p) in smem
        #pragma unroll
        for (int it = 0; it < 8; it++) {
            int row = it * 8 + lrow;
            size_t off = (size_t)row * SKDIM + s0 + lcol;
            uint2 xh = *(const uint2*)&shb[off];
            uint2 xl = *(const uint2*)&slb[off];
            float2 rs = *(const float2*)(smem + RS + row * 8);
            float x0 = __bfloat162float(__ushort_as_bfloat16((uint16_t)(xh.x & 0xffff))) +
                       __bfloat162float(__ushort_as_bfloat16((uint16_t)(xl.x & 0xffff)));
            float x1 = __bfloat162float(__ushort_as_bfloat16((uint16_t)(xh.x >> 16))) +
                       __bfloat162float(__ushort_as_bfloat16((uint16_t)(xl.x >> 16)));
            float x2 = __bfloat162float(__ushort_as_bfloat16((uint16_t)(xh.y & 0xffff))) +
                       __bfloat162float(__ushort_as_bfloat16((uint16_t)(xl.y & 0xffff)));
            float x3 = __bfloat162float(__ushort_as_bfloat16((uint16_t)(xh.y >> 16))) +
                       __bfloat162float(__ushort_as_bfloat16((uint16_t)(xl.y >> 16)));
            float4 p;
            p.x = __expf(x0 - rs.x) * rs.y;
            p.y = __expf(x1 - rs.x) * rs.y;
            p.z = __expf(x2 - rs.x) * rs.y;
            p.w = __expf(x3 - rs.x) * rs.y;
            *(float4*)(attnb + off) = p;
            uint32_t h0, l0, h1, l1;
            split2(p.x, p.y, h0, l0);
            split2(p.z, p.w, h1, l1);
            uint32_t so = sw128((uint32_t)row * 128 + ch * 2);
            *(uint2*)(smem + PHb + so) = make_uint2(h0, h1);
            *(uint2*)(smem + PLb + so) = make_uint2(l0, l1);
        }
        cp_wait0();       // V(st) resident
        __syncthreads();

        // L2-prefetch next tile's scores (overlaps MMA below)
        if (st + 1 < SPLIT_S / 128) {
            const int sn = s0 + 128;
            #pragma unroll
            for (int it = 0; it < 8; it++) {
                int row = it * 8 + lrow;
                size_t off = (size_t)row * SKDIM + sn + lcol;
                l2_prefetch(&shb[off]);
                l2_prefetch(&slb[off]);
            }
        }

        // AV: P(64x128) @ V^T(64x128) -> acc (64x64)
        #pragma unroll
        for (int half = 0; half < 2; half++) {
            const uint32_t PH = half ? P1H : P0H;
            const uint32_t PL = half ? P1L : P0L;
            const uint32_t VH = half ? V1H : V0H;
            const uint32_t VL = half ? V1L : V0L;
            #pragma unroll
            for (int ks = 0; ks < 4; ks++) {
                uint32_t ah[4], al[4];
                uint32_t aa = a_addr(mrow0, ks, lane);
                ldm_x4(ah, sb + PH + aa);
                ldm_x4(al, sb + PL + aa);
                #pragma unroll
                for (int ntp = 0; ntp < 2; ntp++) {
                    uint32_t bh[4], bl[4];
                    uint32_t ba = b_addr(ncol0 + ntp * 16, ks, lane);
                    ldm_x4(bh, sb + VH + ba);
                    ldm_x4(bl, sb + VL + ba);
                    mma_bf16(acc_av[ntp * 2 + 0], ah, &bh[0]);
                    mma_bf16(acc_av[ntp * 2 + 0], al, &bh[0]);
                    mma_bf16(acc_av[ntp * 2 + 0], ah, &bl[0]);
                    mma_bf16(acc_av[ntp * 2 + 1], ah, &bh[2]);
                    mma_bf16(acc_av[ntp * 2 + 1], al, &bh[2]);
                    mma_bf16(acc_av[ntp * 2 + 1], ah, &bl[2]);
                }
            }
        }
        __syncthreads();  // smem reuse next iteration
    }

    // write split-K partial
    float* op = opart + (size_t)sp * (BATCH * SQDIM * KDIM);
    #pragma unroll
    for (int nt = 0; nt < 4; nt++) {
        #pragma unroll
        for (int rh = 0; rh < 2; rh++) {
            int m = q0 + mrow0 + (lane >> 2) + rh * 8;
            int c = ncol0 + nt * 8 + (lane & 3) * 2;
            *(float2*)&op[((size_t)b * SQDIM + m) * KDIM + c] =
                make_float2(acc_av[nt][rh * 2 + 0], acc_av[nt][rh * 2 + 1]);
        }
    }
}

// ---------------------------------------------------------------------------
// Reduce split-K partials -> oc bf16 hi/lo
// ---------------------------------------------------------------------------
__global__ __launch_bounds__(256) void reduce_oc(
    const float* __restrict__ opart,
    __nv_bfloat16* __restrict__ och, __nv_bfloat16* __restrict__ ocl)
{
    const size_t i = ((size_t)blockIdx.x * 256 + threadIdx.x) * 2;
    const size_t STRIDE = (size_t)BATCH * SQDIM * KDIM;
    float a = 0.f, c = 0.f;
    #pragma unroll
    for (int s = 0; s < NSPLIT; s++) {
        float2 v = *(const float2*)&opart[s * STRIDE + i];
        a += v.x;
        c += v.y;
    }
    uint32_t hi, lo;
    split2(a, c, hi, lo);
    *(uint32_t*)&och[i] = hi;
    *(uint32_t*)&ocl[i] = lo;
}

// ---------------------------------------------------------------------------
// Out-proj (mma.sync): out[m][h] = oc[m] . W_out[h] + bias[h]
// CTA 128m x 128h, K = 64. 8 warps (4m x 2n), warp 32x64.
// ---------------------------------------------------------------------------
__global__ __launch_bounds__(256) void oproj_mma(
    const __nv_bfloat16* __restrict__ och, const __nv_bfloat16* __restrict__ ocl,
    const float* __restrict__ W, const float* __restrict__ bias,
    float* __restrict__ out)
{
    extern __shared__ char smem[];
    const uint32_t sb = smem_u32(smem);
    const uint32_t AH = 0, AL = 16384, BH = 32768, BL = 49152;
    const int tid = threadIdx.x, wid = tid >> 5, lane = tid & 31;
    const int m0 = blockIdx.y * 128, n0 = blockIdx.x * 128;

    #pragma unroll
    for (int i = tid; i < 1024; i += 256) {
        int r = i >> 3, c = i & 7;
        uint32_t so = sw128((uint32_t)r * 128 + c * 16);
        *(uint4*)(smem + AH + so) = *(const uint4*)&och[(size_t)(m0 + r) * KDIM + c * 8];
        *(uint4*)(smem + AL + so) = *(const uint4*)&ocl[(size_t)(m0 + r) * KDIM + c * 8];
    }
    #pragma unroll 2
    for (int i = tid; i < 2048; i += 256) {
        int r = i >> 4, c4 = i & 15;
        float4 wv = *(const float4*)&W[(size_t)(n0 + r) * KDIM + c4 * 4];
        uint32_t h0, l0, h1, l1;
        split2(wv.x, wv.y, h0, l0);
        split2(wv.z, wv.w, h1, l1);
        uint32_t so = sw128((uint32_t)r * 128 + c4 * 8);
        *(uint2*)(smem + BH + so) = make_uint2(h0, h1);
        *(uint2*)(smem + BL + so) = make_uint2(l0, l1);
    }
    __syncthreads();

    const int wm = wid >> 1, wn = wid & 1;
    const int mrow0 = wm * 32, ncol0 = wn * 64;
    float acc[2][8][4] = {};

    #pragma unroll
    for (int ks = 0; ks < 4; ks++) {
        uint32_t ah[2][4], al[2][4];
        #pragma unroll
        for (int mt = 0; mt < 2; mt++) {
            uint32_t aa = a_addr(mrow0 + mt * 16, ks, lane);
            ldm_x4(ah[mt], sb + AH + aa);
            ldm_x4(al[mt], sb + AL + aa);
        }
        #pragma unroll
        for (int ntp = 0; ntp < 4; ntp++) {
            uint32_t bh[4], bl[4];
            uint32_t ba = b_addr(ncol0 + ntp * 16, ks, lane);
            ldm_x4(bh, sb + BH + ba);
            ldm_x4(bl, sb + BL + ba);
            #pragma unroll
            for (int mt = 0; mt < 2; mt++) {
                mma_bf16(acc[mt][ntp * 2 + 0], ah[mt], &bh[0]);
                mma_bf16(acc[mt][ntp * 2 + 0], al[mt], &bh[0]);
                mma_bf16(acc[mt][ntp * 2 + 0], ah[mt], &bl[0]);
                mma_bf16(acc[mt][ntp * 2 + 1], ah[mt], &bh[2]);
                mma_bf16(acc[mt][ntp * 2 + 1], al[mt], &bh[2]);
                mma_bf16(acc[mt][ntp * 2 + 1], ah[mt], &bl[2]);
            }
        }
    }

    #pragma unroll
    for (int mt = 0; mt < 2; mt++) {
        #pragma unroll
        for (int nt = 0; nt < 8; nt++) {
            #pragma unroll
            for (int rh = 0; rh < 2; rh++) {
                int m = m0 + mrow0 + mt * 16 + (lane >> 2) + rh * 8;
                int h = n0 + ncol0 + nt * 8 + (lane & 3) * 2;
                float2 o;
                o.x = acc[mt][nt][rh * 2 + 0] + bias[h];
                o.y = acc[mt][nt][rh * 2 + 1] + bias[h + 1];
                *(float2*)&out[(size_t)m * HIDDEN + h] = o;
            }
        }
    }
}

// ---------------------------------------------------------------------------
extern "C" void kernel_launch(void* const* d_in, const int* in_sizes, int n_in,
                              void* d_out, int out_size)
{
    const float* query  = (const float*)d_in[0];
    const float* key    = (const float*)d_in[1];
    const float* value  = (const float*)d_in[2];
    const float* Wq     = (const float*)d_in[3];
    const float* Wk     = (const float*)d_in[4];
    const float* Wv     = (const float*)d_in[5];
    const float* q_mean = (const float*)d_in[6];
    const float* k_mean = (const float*)d_in[7];
    const float* v_mean = (const float*)d_in[8];
    const float* W_out  = (const float*)d_in[9];
    const float* b_out  = (const float*)d_in[10];

    float* out_ptr  = (float*)d_out;
    float* attn_ptr = (float*)d_out + (size_t)BATCH * SQDIM * HIDDEN;

    __nv_bfloat16 *qh, *ql, *kh, *kl, *vth, *vtl, *och, *ocl, *sh, *sl;
    float *opart;
    float2 *part, *rows;
    cudaGetSymbolAddress((void**)&qh, g_qh);
    cudaGetSymbolAddress((void**)&ql, g_ql);
    cudaGetSymbolAddress((void**)&kh, g_kh);
    cudaGetSymbolAddress((void**)&kl, g_kl);
    cudaGetSymbolAddress((void**)&vth, g_vth);
    cudaGetSymbolAddress((void**)&vtl, g_vtl);
    cudaGetSymbolAddress((void**)&och, g_och);
    cudaGetSymbolAddress((void**)&ocl, g_ocl);
    cudaGetSymbolAddress((void**)&sh, g_sh);
    cudaGetSymbolAddress((void**)&sl, g_sl);
    cudaGetSymbolAddress((void**)&opart, g_opart);
    cudaGetSymbolAddress((void**)&part, g_part);
    cudaGetSymbolAddress((void**)&rows, g_rows);

    cudaFuncSetAttribute(proj3_mma, cudaFuncAttributeMaxDynamicSharedMemorySize, 32768);
    cudaFuncSetAttribute(scores_mma, cudaFuncAttributeMaxDynamicSharedMemorySize, 65536);
    cudaFuncSetAttribute(av2_mma, cudaFuncAttributeMaxDynamicSharedMemorySize, 66048);
    cudaFuncSetAttribute(oproj_mma, cudaFuncAttributeMaxDynamicSharedMemorySize, 65536);

    const int Mrows = BATCH * SQDIM;  // 16384

    dim3 pg(Mrows / 64, 3);
    proj3_mma<<<pg, 256, 32768>>>(query, key, value, Wq, Wk, Wv,
                                  q_mean, k_mean, v_mean,
                                  qh, ql, kh, kl, vth, vtl);

    dim3 sg(SKDIM / 128, SQDIM / 128, BATCH);
    scores_mma<<<sg, 256, 65536>>>(qh, ql, kh, kl, sh, sl, part);

    rowstats_kernel<<<Mrows / 8, 256>>>(part, rows);

    dim3 fg(SQDIM / 64, NSPLIT, BATCH);
    av2_mma<<<fg, 256, 66048>>>(sh, sl, attn_ptr, vth, vtl, rows, opart);

    reduce_oc<<<(Mrows * KDIM / 2) / 256, 256>>>(opart, och, ocl);

    dim3 og(HIDDEN / 128, Mrows / 128);
    oproj_mma<<<og, 256, 65536>>>(och, ocl, W_out, b_out, out_ptr);
}

// round 16
// speedup vs baseline: 1.1346x; 1.1346x over previous
#include <cuda_runtime.h>
#include <cuda_bf16.h>
#include <cstdint>
#include <math.h>

#define HIDDEN 1024
#define KDIM 64
#define BATCH 4
#define SQDIM 4096
#define SKDIM 4096
#define NSPLIT 8
#define SPLIT_S (SKDIM / NSPLIT)   // 512

// ---------------- device scratch (no allocation allowed) --------------------
__device__ __nv_bfloat16 g_qh[BATCH * SQDIM * KDIM];
__device__ __nv_bfloat16 g_ql[BATCH * SQDIM * KDIM];
__device__ __nv_bfloat16 g_kh[BATCH * SKDIM * KDIM];
__device__ __nv_bfloat16 g_kl[BATCH * SKDIM * KDIM];
__device__ __nv_bfloat16 g_vth[BATCH * KDIM * SKDIM];  // V^T: [b][j][s]
__device__ __nv_bfloat16 g_vtl[BATCH * KDIM * SKDIM];
__device__ __nv_bfloat16 g_och[BATCH * SQDIM * KDIM];
__device__ __nv_bfloat16 g_ocl[BATCH * SQDIM * KDIM];
__device__ float  g_opart[(size_t)NSPLIT * BATCH * SQDIM * KDIM];
__device__ float2 g_part[(size_t)BATCH * SQDIM * 64];
__device__ float2 g_rows[BATCH * SQDIM];

// ---------------- helpers ---------------------------------------------------
__device__ __forceinline__ uint32_t smem_u32(const void* p) {
    uint32_t a;
    asm("{ .reg .u64 t; cvta.to.shared.u64 t, %1; cvt.u32.u64 %0, t; }"
        : "=r"(a) : "l"(p));
    return a;
}
__device__ __forceinline__ uint32_t sw128(uint32_t x) { return x ^ ((x >> 3) & 0x70); }

__device__ __forceinline__ void ldm_x4(uint32_t* r, uint32_t addr) {
    asm volatile("ldmatrix.sync.aligned.m8n8.x4.shared.b16 {%0,%1,%2,%3}, [%4];"
                 : "=r"(r[0]), "=r"(r[1]), "=r"(r[2]), "=r"(r[3]) : "r"(addr));
}
__device__ __forceinline__ void mma_bf16(float* d, const uint32_t* a, const uint32_t* b) {
    asm volatile(
        "mma.sync.aligned.m16n8k16.row.col.f32.bf16.bf16.f32 "
        "{%0,%1,%2,%3}, {%4,%5,%6,%7}, {%8,%9}, {%0,%1,%2,%3};"
        : "+f"(d[0]), "+f"(d[1]), "+f"(d[2]), "+f"(d[3])
        : "r"(a[0]), "r"(a[1]), "r"(a[2]), "r"(a[3]), "r"(b[0]), "r"(b[1]));
}
__device__ __forceinline__ uint32_t pack_bf(__nv_bfloat16 a, __nv_bfloat16 b) {
    return ((uint32_t)__bfloat16_as_ushort(b) << 16) | __bfloat16_as_ushort(a);
}
__device__ __forceinline__ void split2(float x, float y, uint32_t& hi, uint32_t& lo) {
    __nv_bfloat16 hx = __float2bfloat16(x), hy = __float2bfloat16(y);
    __nv_bfloat16 lx = __float2bfloat16(x - __bfloat162float(hx));
    __nv_bfloat16 ly = __float2bfloat16(y - __bfloat162float(hy));
    hi = pack_bf(hx, hy);
    lo = pack_bf(lx, ly);
}
__device__ __forceinline__ void l2_prefetch(const void* p) {
    asm volatile("prefetch.global.L2 [%0];" :: "l"(p));
}
__device__ __forceinline__ void cp_async16(uint32_t smem_addr, const void* gptr) {
    asm volatile("cp.async.cg.shared.global [%0], [%1], 16;"
                 :: "r"(smem_addr), "l"(gptr) : "memory");
}
__device__ __forceinline__ void cp_commit() {
    asm volatile("cp.async.commit_group;" ::: "memory");
}
__device__ __forceinline__ void cp_wait0() {
    asm volatile("cp.async.wait_group 0;" ::: "memory");
}
__device__ __forceinline__ void stg_cs_f4(float* p, float4 v) {
    asm volatile("st.global.cs.v4.f32 [%0], {%1,%2,%3,%4};"
                 :: "l"(p), "f"(v.x), "f"(v.y), "f"(v.z), "f"(v.w) : "memory");
}
__device__ __forceinline__ void stg_cs_f2(float* p, float2 v) {
    asm volatile("st.global.cs.v2.f32 [%0], {%1,%2};"
                 :: "l"(p), "f"(v.x), "f"(v.y) : "memory");
}
// A-fragment ldmatrix address (16x16 tile in a [rows][64bf16] sw128 tile)
__device__ __forceinline__ uint32_t a_addr(int row0, int ks, int lane) {
    int r = row0 + (lane & 15);
    int off = ks * 32 + ((lane >> 4) << 4);
    return sw128((uint32_t)r * 128 + off);
}
// B-pair fragment (two n-tiles of 8): rows are n (or s) of an n×k layout
__device__ __forceinline__ uint32_t b_addr(int row0, int ks, int lane) {
    int r = row0 + ((lane >> 4) << 3) + (lane & 7);
    int off = ks * 32 + (((lane >> 3) & 1) << 4);
    return sw128((uint32_t)r * 128 + off);
}

// ---------------------------------------------------------------------------
// Projection x3 merged (mma.sync): out = (x - mean) @ W^T -> bf16 hi/lo
// gridDim = (Mrows/64, 3): y selects q/k/v. v output is transposed.
// ---------------------------------------------------------------------------
__global__ __launch_bounds__(256) void proj3_mma(
    const float* __restrict__ xq, const float* __restrict__ xk,
    const float* __restrict__ xv,
    const float* __restrict__ Wq, const float* __restrict__ Wk,
    const float* __restrict__ Wv,
    const float* __restrict__ mq, const float* __restrict__ mk,
    const float* __restrict__ mv,
    __nv_bfloat16* __restrict__ qh, __nv_bfloat16* __restrict__ ql,
    __nv_bfloat16* __restrict__ kh, __nv_bfloat16* __restrict__ kl,
    __nv_bfloat16* __restrict__ vth, __nv_bfloat16* __restrict__ vtl)
{
    extern __shared__ char smem[];
    const uint32_t sb = smem_u32(smem);
    const uint32_t AH = 0, AL = 8192, BH = 16384, BL = 24576;
    const int tid = threadIdx.x, wid = tid >> 5, lane = tid & 31;
    const int m0 = blockIdx.x * 64;
    const int sel = blockIdx.y;

    const float* x    = sel == 0 ? xq : (sel == 1 ? xk : xv);
    const float* W    = sel == 0 ? Wq : (sel == 1 ? Wk : Wv);
    const float* mean = sel == 0 ? mq : (sel == 1 ? mk : mv);
    __nv_bfloat16* outh = sel == 0 ? qh : (sel == 1 ? kh : vth);
    __nv_bfloat16* outl = sel == 0 ? ql : (sel == 1 ? kl : vtl);
    const bool trans = (sel == 2);

    const int wm = wid >> 1, wn = wid & 1;
    const int mrow0 = wm * 16, ncol0 = wn * 32;
    float acc[4][4] = {};

    for (int k0 = 0; k0 < HIDDEN; k0 += 64) {
        #pragma unroll
        for (int i = tid; i < 1024; i += 256) {
            int r = i >> 4, c4 = i & 15;
            float4 xv4 = *(const float4*)&x[(size_t)(m0 + r) * HIDDEN + k0 + c4 * 4];
            float4 mn = *(const float4*)&mean[k0 + c4 * 4];
            uint32_t h0, l0, h1, l1;
            split2(xv4.x - mn.x, xv4.y - mn.y, h0, l0);
            split2(xv4.z - mn.z, xv4.w - mn.w, h1, l1);
            uint32_t so = sw128((uint32_t)r * 128 + c4 * 8);
            *(uint2*)(smem + AH + so) = make_uint2(h0, h1);
            *(uint2*)(smem + AL + so) = make_uint2(l0, l1);
        }
        #pragma unroll
        for (int i = tid; i < 1024; i += 256) {
            int r = i >> 4, c4 = i & 15;
            float4 wv = *(const float4*)&W[(size_t)r * HIDDEN + k0 + c4 * 4];
            uint32_t h0, l0, h1, l1;
            split2(wv.x, wv.y, h0, l0);
            split2(wv.z, wv.w, h1, l1);
            uint32_t so = sw128((uint32_t)r * 128 + c4 * 8);
            *(uint2*)(smem + BH + so) = make_uint2(h0, h1);
            *(uint2*)(smem + BL + so) = make_uint2(l0, l1);
        }
        __syncthreads();

        #pragma unroll
        for (int ks = 0; ks < 4; ks++) {
            uint32_t ah[4], al[4];
            uint32_t aa = a_addr(mrow0, ks, lane);
            ldm_x4(ah, sb + AH + aa);
            ldm_x4(al, sb + AL + aa);
            #pragma unroll
            for (int ntp = 0; ntp < 2; ntp++) {
                uint32_t bh[4], bl[4];
                uint32_t ba = b_addr(ncol0 + ntp * 16, ks, lane);
                ldm_x4(bh, sb + BH + ba);
                ldm_x4(bl, sb + BL + ba);
                mma_bf16(acc[ntp * 2 + 0], ah, &bh[0]);
                mma_bf16(acc[ntp * 2 + 0], al, &bh[0]);
                mma_bf16(acc[ntp * 2 + 0], ah, &bl[0]);
                mma_bf16(acc[ntp * 2 + 1], ah, &bh[2]);
                mma_bf16(acc[ntp * 2 + 1], al, &bh[2]);
                mma_bf16(acc[ntp * 2 + 1], ah, &bl[2]);
            }
        }
        __syncthreads();
    }

    #pragma unroll
    for (int nt = 0; nt < 4; nt++) {
        #pragma unroll
        for (int rh = 0; rh < 2; rh++) {
            int m = m0 + mrow0 + (lane >> 2) + rh * 8;
            int c = ncol0 + nt * 8 + (lane & 3) * 2;
            uint32_t hi, lo;
            split2(acc[nt][rh * 2 + 0], acc[nt][rh * 2 + 1], hi, lo);
            if (trans) {
                int b = m >> 12, s = m & 4095;
                size_t i0 = (size_t)b * KDIM * SKDIM + (size_t)c * SKDIM + s;
                size_t i1 = i0 + SKDIM;
                outh[i0] = __ushort_as_bfloat16((uint16_t)(hi & 0xffff));
                outh[i1] = __ushort_as_bfloat16((uint16_t)(hi >> 16));
                outl[i0] = __ushort_as_bfloat16((uint16_t)(lo & 0xffff));
                outl[i1] = __ushort_as_bfloat16((uint16_t)(lo >> 16));
            } else {
                *(uint32_t*)&outh[(size_t)m * KDIM + c] = hi;
                *(uint32_t*)&outl[(size_t)m * KDIM + c] = lo;
            }
        }
    }
}

// ---------------------------------------------------------------------------
// Pass 1: scores MMA -> raw scaled scores into attn region + softmax partials
// CTA tile 128q x 128s, 8 warps (4m x 2n), warp tile 32x64.
// ---------------------------------------------------------------------------
__global__ __launch_bounds__(256) void scores_mma(
    const __nv_bfloat16* __restrict__ qh, const __nv_bfloat16* __restrict__ ql,
    const __nv_bfloat16* __restrict__ kh, const __nv_bfloat16* __restrict__ kl,
    float* __restrict__ attn, float2* __restrict__ part)
{
    extern __shared__ char smem[];
    const uint32_t sb = smem_u32(smem);
    const uint32_t QH = 0, QL = 16384, KH = 32768, KL = 49152;
    const int tid = threadIdx.x, wid = tid >> 5, lane = tid & 31;
    const int b = blockIdx.z, q0 = blockIdx.y * 128, s0 = blockIdx.x * 128;

    const size_t qoff = ((size_t)b * SQDIM + q0) * KDIM;
    const size_t koff = ((size_t)b * SKDIM + s0) * KDIM;
    #pragma unroll
    for (int i = tid; i < 1024; i += 256) {
        int r = i >> 3, c = i & 7;
        uint32_t so = sw128((uint32_t)r * 128 + c * 16);
        *(uint4*)(smem + QH + so) = *(const uint4*)&qh[qoff + (size_t)r * KDIM + c * 8];
        *(uint4*)(smem + QL + so) = *(const uint4*)&ql[qoff + (size_t)r * KDIM + c * 8];
        *(uint4*)(smem + KH + so) = *(const uint4*)&kh[koff + (size_t)r * KDIM + c * 8];
        *(uint4*)(smem + KL + so) = *(const uint4*)&kl[koff + (size_t)r * KDIM + c * 8];
    }
    __syncthreads();

    const int wm = wid >> 1, wn = wid & 1;
    const int mrow0 = wm * 32, ncol0 = wn * 64;
    float acc[2][8][4] = {};

    #pragma unroll
    for (int ks = 0; ks < 4; ks++) {
        uint32_t ah[2][4], al[2][4];
        #pragma unroll
        for (int mt = 0; mt < 2; mt++) {
            uint32_t aa = a_addr(mrow0 + mt * 16, ks, lane);
            ldm_x4(ah[mt], sb + QH + aa);
            ldm_x4(al[mt], sb + QL + aa);
        }
        #pragma unroll
        for (int ntp = 0; ntp < 4; ntp++) {
            uint32_t bh[4], bl[4];
            uint32_t ba = b_addr(ncol0 + ntp * 16, ks, lane);
            ldm_x4(bh, sb + KH + ba);
            ldm_x4(bl, sb + KL + ba);
            #pragma unroll
            for (int mt = 0; mt < 2; mt++) {
                mma_bf16(acc[mt][ntp * 2 + 0], ah[mt], &bh[0]);
                mma_bf16(acc[mt][ntp * 2 + 0], al[mt], &bh[0]);
                mma_bf16(acc[mt][ntp * 2 + 0], ah[mt], &bl[0]);
                mma_bf16(acc[mt][ntp * 2 + 1], ah[mt], &bh[2]);
                mma_bf16(acc[mt][ntp * 2 + 1], al[mt], &bh[2]);
                mma_bf16(acc[mt][ntp * 2 + 1], ah[mt], &bl[2]);
            }
        }
    }

    const int stile = blockIdx.x * 2 + wn;
    #pragma unroll
    for (int mt = 0; mt < 2; mt++) {
        #pragma unroll
        for (int rh = 0; rh < 2; rh++) {
            int qrow = q0 + mrow0 + mt * 16 + (lane >> 2) + rh * 8;
            float* arow = attn + ((size_t)b * SQDIM + qrow) * SKDIM + s0 + ncol0;
            float v[16];
            float m = -3.4e38f;
            #pragma unroll
            for (int nt = 0; nt < 8; nt++) {
                v[nt * 2 + 0] = acc[mt][nt][rh * 2 + 0] * 0.125f;
                v[nt * 2 + 1] = acc[mt][nt][rh * 2 + 1] * 0.125f;
                m = fmaxf(m, fmaxf(v[nt * 2], v[nt * 2 + 1]));
                *(float2*)&arow[nt * 8 + (lane & 3) * 2] = make_float2(v[nt * 2], v[nt * 2 + 1]);
            }
            m = fmaxf(m, __shfl_xor_sync(0xffffffffu, m, 1));
            m = fmaxf(m, __shfl_xor_sync(0xffffffffu, m, 2));
            float s = 0.f;
            #pragma unroll
            for (int c = 0; c < 16; c++) s += __expf(v[c] - m);
            s += __shfl_xor_sync(0xffffffffu, s, 1);
            s += __shfl_xor_sync(0xffffffffu, s, 2);
            if ((lane & 3) == 0)
                part[((size_t)b * SQDIM + qrow) * 64 + stile] = make_float2(m, s);
        }
    }
}

// ---------------------------------------------------------------------------
// Combine 64 per-tile partials -> per-row (max, 1/sum). Warp per row.
// ---------------------------------------------------------------------------
__global__ __launch_bounds__(256) void rowstats_kernel(
    const float2* __restrict__ part, float2* __restrict__ rows)
{
    const int row = blockIdx.x * 8 + (threadIdx.x >> 5);
    const int lane = threadIdx.x & 31;
    float2 p0 = part[(size_t)row * 64 + lane];
    float2 p1 = part[(size_t)row * 64 + 32 + lane];
    float m = fmaxf(p0.x, p1.x);
    float s = p0.y * __expf(p0.x - m) + p1.y * __expf(p1.x - m);
    #pragma unroll
    for (int o = 16; o; o >>= 1) {
        float om = __shfl_xor_sync(0xffffffffu, m, o);
        float os = __shfl_xor_sync(0xffffffffu, s, o);
        float nm = fmaxf(m, om);
        s = s * __expf(m - nm) + os * __expf(om - nm);
        m = nm;
    }
    if (lane == 0) rows[row] = make_float2(m, 1.0f / s);
}

// ---------------------------------------------------------------------------
// Pass 2 (R14 structure): normalize raw scores in place -> final attn, then
// p@V^T into split-K partials. CTA = 64q x 512s-split, 256 threads.
// V via cp.async; next-tile score L2 prefetch hoisted to loop top;
// attn + opart stores use .cs (evict-first) to protect prefetched scores.
// smem: P0H 0 | P0L 8K | P1H 16K | P1L 24K | V0H 32K | V0L 40K |
//       V1H 48K | V1L 56K | RS 64K  (total ~64.5K)
// ---------------------------------------------------------------------------
__global__ __launch_bounds__(256) void av2_mma(
    float* __restrict__ attn,
    const __nv_bfloat16* __restrict__ vth, const __nv_bfloat16* __restrict__ vtl,
    const float2* __restrict__ rows, float* __restrict__ opart)
{
    extern __shared__ char smem[];
    const uint32_t sb = smem_u32(smem);
    const uint32_t P0H = 0, P0L = 8192, P1H = 16384, P1L = 24576;
    const uint32_t V0H = 32768, V0L = 40960, V1H = 49152, V1L = 57344;
    const uint32_t RS = 65536;
    const int tid = threadIdx.x, wid = tid >> 5, lane = tid & 31;
    const int qt = blockIdx.x, sp = blockIdx.y, b = blockIdx.z;
    const int q0 = qt * 64;

    if (tid < 64)
        *(float2*)(smem + RS + tid * 8) = rows[(size_t)b * SQDIM + q0 + tid];

    const __nv_bfloat16* vhb = vth + (size_t)b * KDIM * SKDIM;
    const __nv_bfloat16* vlb = vtl + (size_t)b * KDIM * SKDIM;
    float* attnb = attn + ((size_t)b * SQDIM + q0) * SKDIM;

    // normalize-loop addressing: 64 rows x 128 cols, 8 float4 per thread
    const int lrow = tid >> 5;           // 0..7
    const int lcol = lane * 4;           // 0..124
    const int halfsel = lcol >> 6;       // 0 or 1
    const int ch = lcol & 63;
    const uint32_t PHb = halfsel ? P1H : P0H;
    const uint32_t PLb = halfsel ? P1L : P0L;

    const int wm = wid >> 1, wn = wid & 1;
    const int mrow0 = wm * 16, ncol0 = wn * 32;
    float acc_av[4][4] = {};

    __syncthreads();  // RS visible

    for (int st = 0; st < SPLIT_S / 128; st++) {
        const int s0 = sp * SPLIT_S + st * 128;

        // V tiles via cp.async (overlap with normalize phase below)
        #pragma unroll
        for (int i = tid; i < 512; i += 256) {
            int j = i >> 3, c = i & 7;
            uint32_t so = sw128((uint32_t)j * 128 + c * 16);
            const size_t g0 = (size_t)j * SKDIM + s0 + c * 8;
            cp_async16(sb + V0H + so, &vhb[g0]);
            cp_async16(sb + V0L + so, &vlb[g0]);
            cp_async16(sb + V1H + so, &vhb[g0 + 64]);
            cp_async16(sb + V1L + so, &vlb[g0 + 64]);
        }
        cp_commit();

        // L2-prefetch NEXT tile's scores now — hidden under normalize + MMA
        if (st + 1 < SPLIT_S / 128) {
            const int sn = s0 + 128;
            #pragma unroll
            for (int it = 0; it < 8; it++) {
                int row = it * 8 + lrow;
                l2_prefetch(attnb + (size_t)row * SKDIM + sn + lcol);
            }
        }

        // normalize: read raw scores, p = exp(s-m)*inv, write attn (.cs),
        // stage P in smem
        #pragma unroll
        for (int it = 0; it < 8; it++) {
            int row = it * 8 + lrow;
            float* ap = attnb + (size_t)row * SKDIM + s0 + lcol;
            float4 x = *(const float4*)ap;
            float2 rs = *(const float2*)(smem + RS + row * 8);
            float4 p;
            p.x = __expf(x.x - rs.x) * rs.y;
            p.y = __expf(x.y - rs.x) * rs.y;
            p.z = __expf(x.z - rs.x) * rs.y;
            p.w = __expf(x.w - rs.x) * rs.y;
            stg_cs_f4(ap, p);
            uint32_t h0, l0, h1, l1;
            split2(p.x, p.y, h0, l0);
            split2(p.z, p.w, h1, l1);
            uint32_t so = sw128((uint32_t)row * 128 + ch * 2);
            *(uint2*)(smem + PHb + so) = make_uint2(h0, h1);
            *(uint2*)(smem + PLb + so) = make_uint2(l0, l1);
        }
        cp_wait0();       // V(st) resident
        __syncthreads();

        // AV: P(64x128) @ V^T(64x128) -> acc (64x64)
        #pragma unroll
        for (int half = 0; half < 2; half++) {
            const uint32_t PH = half ? P1H : P0H;
            const uint32_t PL = half ? P1L : P0L;
            const uint32_t VH = half ? V1H : V0H;
            const uint32_t VL = half ? V1L : V0L;
            #pragma unroll
            for (int ks = 0; ks < 4; ks++) {
                uint32_t ah[4], al[4];
                uint32_t aa = a_addr(mrow0, ks, lane);
                ldm_x4(ah, sb + PH + aa);
                ldm_x4(al, sb + PL + aa);
                #pragma unroll
                for (int ntp = 0; ntp < 2; ntp++) {
                    uint32_t bh[4], bl[4];
                    uint32_t ba = b_addr(ncol0 + ntp * 16, ks, lane);
                    ldm_x4(bh, sb + VH + ba);
                    ldm_x4(bl, sb + VL + ba);
                    mma_bf16(acc_av[ntp * 2 + 0], ah, &bh[0]);
                    mma_bf16(acc_av[ntp * 2 + 0], al, &bh[0]);
                    mma_bf16(acc_av[ntp * 2 + 0], ah, &bl[0]);
                    mma_bf16(acc_av[ntp * 2 + 1], ah, &bh[2]);
                    mma_bf16(acc_av[ntp * 2 + 1], al, &bh[2]);
                    mma_bf16(acc_av[ntp * 2 + 1], ah, &bl[2]);
                }
            }
        }
        __syncthreads();  // smem reuse next iteration
    }

    // write split-K partial (.cs — read once by reduce)
    float* op = opart + (size_t)sp * (BATCH * SQDIM * KDIM);
    #pragma unroll
    for (int nt = 0; nt < 4; nt++) {
        #pragma unroll
        for (int rh = 0; rh < 2; rh++) {
            int m = q0 + mrow0 + (lane >> 2) + rh * 8;
            int c = ncol0 + nt * 8 + (lane & 3) * 2;
            stg_cs_f2(&op[((size_t)b * SQDIM + m) * KDIM + c],
                      make_float2(acc_av[nt][rh * 2 + 0], acc_av[nt][rh * 2 + 1]));
        }
    }
}

// ---------------------------------------------------------------------------
// Reduce split-K partials -> oc bf16 hi/lo
// ---------------------------------------------------------------------------
__global__ __launch_bounds__(256) void reduce_oc(
    const float* __restrict__ opart,
    __nv_bfloat16* __restrict__ och, __nv_bfloat16* __restrict__ ocl)
{
    const size_t i = ((size_t)blockIdx.x * 256 + threadIdx.x) * 2;
    const size_t STRIDE = (size_t)BATCH * SQDIM * KDIM;
    float a = 0.f, c = 0.f;
    #pragma unroll
    for (int s = 0; s < NSPLIT; s++) {
        float2 v = *(const float2*)&opart[s * STRIDE + i];
        a += v.x;
        c += v.y;
    }
    uint32_t hi, lo;
    split2(a, c, hi, lo);
    *(uint32_t*)&och[i] = hi;
    *(uint32_t*)&ocl[i] = lo;
}

// ---------------------------------------------------------------------------
// Out-proj (mma.sync): out[m][h] = oc[m] . W_out[h] + bias[h]
// CTA 128m x 128h, K = 64. 8 warps (4m x 2n), warp 32x64.
// ---------------------------------------------------------------------------
__global__ __launch_bounds__(256) void oproj_mma(
    const __nv_bfloat16* __restrict__ och, const __nv_bfloat16* __restrict__ ocl,
    const float* __restrict__ W, const float* __restrict__ bias,
    float* __restrict__ out)
{
    extern __shared__ char smem[];
    const uint32_t sb = smem_u32(smem);
    const uint32_t AH = 0, AL = 16384, BH = 32768, BL = 49152;
    const int tid = threadIdx.x, wid = tid >> 5, lane = tid & 31;
    const int m0 = blockIdx.y * 128, n0 = blockIdx.x * 128;

    #pragma unroll
    for (int i = tid; i < 1024; i += 256) {
        int r = i >> 3, c = i & 7;
        uint32_t so = sw128((uint32_t)r * 128 + c * 16);
        *(uint4*)(smem + AH + so) = *(const uint4*)&och[(size_t)(m0 + r) * KDIM + c * 8];
        *(uint4*)(smem + AL + so) = *(const uint4*)&ocl[(size_t)(m0 + r) * KDIM + c * 8];
    }
    #pragma unroll 2
    for (int i = tid; i < 2048; i += 256) {
        int r = i >> 4, c4 = i & 15;
        float4 wv = *(const float4*)&W[(size_t)(n0 + r) * KDIM + c4 * 4];
        uint32_t h0, l0, h1, l1;
        split2(wv.x, wv.y, h0, l0);
        split2(wv.z, wv.w, h1, l1);
        uint32_t so = sw128((uint32_t)r * 128 + c4 * 8);
        *(uint2*)(smem + BH + so) = make_uint2(h0, h1);
        *(uint2*)(smem + BL + so) = make_uint2(l0, l1);
    }
    __syncthreads();

    const int wm = wid >> 1, wn = wid & 1;
    const int mrow0 = wm * 32, ncol0 = wn * 64;
    float acc[2][8][4] = {};

    #pragma unroll
    for (int ks = 0; ks < 4; ks++) {
        uint32_t ah[2][4], al[2][4];
        #pragma unroll
        for (int mt = 0; mt < 2; mt++) {
            uint32_t aa = a_addr(mrow0 + mt * 16, ks, lane);
            ldm_x4(ah[mt], sb + AH + aa);
            ldm_x4(al[mt], sb + AL + aa);
        }
        #pragma unroll
        for (int ntp = 0; ntp < 4; ntp++) {
            uint32_t bh[4], bl[4];
            uint32_t ba = b_addr(ncol0 + ntp * 16, ks, lane);
            ldm_x4(bh, sb + BH + ba);
            ldm_x4(bl, sb + BL + ba);
            #pragma unroll
            for (int mt = 0; mt < 2; mt++) {
                mma_bf16(acc[mt][ntp * 2 + 0], ah[mt], &bh[0]);
                mma_bf16(acc[mt][ntp * 2 + 0], al[mt], &bh[0]);
                mma_bf16(acc[mt][ntp * 2 + 0], ah[mt], &bl[0]);
                mma_bf16(acc[mt][ntp * 2 + 1], ah[mt], &bh[2]);
                mma_bf16(acc[mt][ntp * 2 + 1], al[mt], &bh[2]);
                mma_bf16(acc[mt][ntp * 2 + 1], ah[mt], &bl[2]);
            }
        }
    }

    #pragma unroll
    for (int mt = 0; mt < 2; mt++) {
        #pragma unroll
        for (int nt = 0; nt < 8; nt++) {
            #pragma unroll
            for (int rh = 0; rh < 2; rh++) {
                int m = m0 + mrow0 + mt * 16 + (lane >> 2) + rh * 8;
                int h = n0 + ncol0 + nt * 8 + (lane & 3) * 2;
                float2 o;
                o.x = acc[mt][nt][rh * 2 + 0] + bias[h];
                o.y = acc[mt][nt][rh * 2 + 1] + bias[h + 1];
                *(float2*)&out[(size_t)m * HIDDEN + h] = o;
            }
        }
    }
}

// ---------------------------------------------------------------------------
extern "C" void kernel_launch(void* const* d_in, const int* in_sizes, int n_in,
                              void* d_out, int out_size)
{
    const float* query  = (const float*)d_in[0];
    const float* key    = (const float*)d_in[1];
    const float* value  = (const float*)d_in[2];
    const float* Wq     = (const float*)d_in[3];
    const float* Wk     = (const float*)d_in[4];
    const float* Wv     = (const float*)d_in[5];
    const float* q_mean = (const float*)d_in[6];
    const float* k_mean = (const float*)d_in[7];
    const float* v_mean = (const float*)d_in[8];
    const float* W_out  = (const float*)d_in[9];
    const float* b_out  = (const float*)d_in[10];

    float* out_ptr  = (float*)d_out;
    float* attn_ptr = (float*)d_out + (size_t)BATCH * SQDIM * HIDDEN;

    __nv_bfloat16 *qh, *ql, *kh, *kl, *vth, *vtl, *och, *ocl;
    float *opart;
    float2 *part, *rows;
    cudaGetSymbolAddress((void**)&qh, g_qh);
    cudaGetSymbolAddress((void**)&ql, g_ql);
    cudaGetSymbolAddress((void**)&kh, g_kh);
    cudaGetSymbolAddress((void**)&kl, g_kl);
    cudaGetSymbolAddress((void**)&vth, g_vth);
    cudaGetSymbolAddress((void**)&vtl, g_vtl);
    cudaGetSymbolAddress((void**)&och, g_och);
    cudaGetSymbolAddress((void**)&ocl, g_ocl);
    cudaGetSymbolAddress((void**)&opart, g_opart);
    cudaGetSymbolAddress((void**)&part, g_part);
    cudaGetSymbolAddress((void**)&rows, g_rows);

    cudaFuncSetAttribute(proj3_mma, cudaFuncAttributeMaxDynamicSharedMemorySize, 32768);
    cudaFuncSetAttribute(scores_mma, cudaFuncAttributeMaxDynamicSharedMemorySize, 65536);
    cudaFuncSetAttribute(av2_mma, cudaFuncAttributeMaxDynamicSharedMemorySize, 66048);
    cudaFuncSetAttribute(oproj_mma, cudaFuncAttributeMaxDynamicSharedMemorySize, 65536);

    const int Mrows = BATCH * SQDIM;  // 16384

    dim3 pg(Mrows / 64, 3);
    proj3_mma<<<pg, 256, 32768>>>(query, key, value, Wq, Wk, Wv,
                                  q_mean, k_mean, v_mean,
                                  qh, ql, kh, kl, vth, vtl);

    dim3 sg(SKDIM / 128, SQDIM / 128, BATCH);
    scores_mma<<<sg, 256, 65536>>>(qh, ql, kh, kl, attn_ptr, part);

    rowstats_kernel<<<Mrows / 8, 256>>>(part, rows);

    dim3 fg(SQDIM / 64, NSPLIT, BATCH);
    av2_mma<<<fg, 256, 66048>>>(attn_ptr, vth, vtl, rows, opart);

    reduce_oc<<<(Mrows * KDIM / 2) / 256, 256>>>(opart, och, ocl);

    dim3 og(HIDDEN / 128, Mrows / 128);
    oproj_mma<<<og, 256, 65536>>>(och, ocl, W_out, b_out, out_ptr);
}

// round 17
// speedup vs baseline: 1.5639x; 1.3784x over previous
#include <cuda_runtime.h>
#include <cuda_bf16.h>
#include <cstdint>
#include <math.h>

#define HIDDEN 1024
#define KDIM 64
#define BATCH 4
#define SQDIM 4096
#define SKDIM 4096
#define NSPLIT 8
#define SPLIT_S (SKDIM / NSPLIT)   // 512

// ---------------- device scratch (no allocation allowed) --------------------
__device__ __nv_bfloat16 g_qh[BATCH * SQDIM * KDIM];
__device__ __nv_bfloat16 g_ql[BATCH * SQDIM * KDIM];
__device__ __nv_bfloat16 g_kh[BATCH * SKDIM * KDIM];
__device__ __nv_bfloat16 g_kl[BATCH * SKDIM * KDIM];
__device__ __nv_bfloat16 g_vth[BATCH * KDIM * SKDIM];  // V^T: [b][j][s]
__device__ __nv_bfloat16 g_vtl[BATCH * KDIM * SKDIM];
__device__ __nv_bfloat16 g_och[BATCH * SQDIM * KDIM];
__device__ __nv_bfloat16 g_ocl[BATCH * SQDIM * KDIM];
__device__ float  g_opart[(size_t)NSPLIT * BATCH * SQDIM * KDIM];
__device__ float2 g_part[(size_t)BATCH * SQDIM * 64];
__device__ float2 g_rows[BATCH * SQDIM];

// ---------------- helpers ---------------------------------------------------
__device__ __forceinline__ uint32_t smem_u32(const void* p) {
    uint32_t a;
    asm("{ .reg .u64 t; cvta.to.shared.u64 t, %1; cvt.u32.u64 %0, t; }"
        : "=r"(a) : "l"(p));
    return a;
}
__device__ __forceinline__ uint32_t sw128(uint32_t x) { return x ^ ((x >> 3) & 0x70); }

__device__ __forceinline__ void ldm_x4(uint32_t* r, uint32_t addr) {
    asm volatile("ldmatrix.sync.aligned.m8n8.x4.shared.b16 {%0,%1,%2,%3}, [%4];"
                 : "=r"(r[0]), "=r"(r[1]), "=r"(r[2]), "=r"(r[3]) : "r"(addr));
}
__device__ __forceinline__ void mma_bf16(float* d, const uint32_t* a, const uint32_t* b) {
    asm volatile(
        "mma.sync.aligned.m16n8k16.row.col.f32.bf16.bf16.f32 "
        "{%0,%1,%2,%3}, {%4,%5,%6,%7}, {%8,%9}, {%0,%1,%2,%3};"
        : "+f"(d[0]), "+f"(d[1]), "+f"(d[2]), "+f"(d[3])
        : "r"(a[0]), "r"(a[1]), "r"(a[2]), "r"(a[3]), "r"(b[0]), "r"(b[1]));
}
__device__ __forceinline__ uint32_t pack_bf(__nv_bfloat16 a, __nv_bfloat16 b) {
    return ((uint32_t)__bfloat16_as_ushort(b) << 16) | __bfloat16_as_ushort(a);
}
__device__ __forceinline__ void split2(float x, float y, uint32_t& hi, uint32_t& lo) {
    __nv_bfloat16 hx = __float2bfloat16(x), hy = __float2bfloat16(y);
    __nv_bfloat16 lx = __float2bfloat16(x - __bfloat162float(hx));
    __nv_bfloat16 ly = __float2bfloat16(y - __bfloat162float(hy));
    hi = pack_bf(hx, hy);
    lo = pack_bf(lx, ly);
}
__device__ __forceinline__ void l2_prefetch(const void* p) {
    asm volatile("prefetch.global.L2 [%0];" :: "l"(p));
}
__device__ __forceinline__ void cp_async16(uint32_t smem_addr, const void* gptr) {
    asm volatile("cp.async.cg.shared.global [%0], [%1], 16;"
                 :: "r"(smem_addr), "l"(gptr) : "memory");
}
__device__ __forceinline__ void cp_commit() {
    asm volatile("cp.async.commit_group;" ::: "memory");
}
__device__ __forceinline__ void cp_wait0() {
    asm volatile("cp.async.wait_group 0;" ::: "memory");
}
// A-fragment ldmatrix address (16x16 tile in a [rows][64bf16] sw128 tile)
__device__ __forceinline__ uint32_t a_addr(int row0, int ks, int lane) {
    int r = row0 + (lane & 15);
    int off = ks * 32 + ((lane >> 4) << 4);
    return sw128((uint32_t)r * 128 + off);
}
// B-pair fragment (two n-tiles of 8): rows are n (or s) of an n×k layout
__device__ __forceinline__ uint32_t b_addr(int row0, int ks, int lane) {
    int r = row0 + ((lane >> 4) << 3) + (lane & 7);
    int off = ks * 32 + (((lane >> 3) & 1) << 4);
    return sw128((uint32_t)r * 128 + off);
}

// ---------------------------------------------------------------------------
// Projection x3 merged (mma.sync): out = (x - mean) @ W^T -> bf16 hi/lo
// gridDim = (Mrows/64, 3): y selects q/k/v. v output is transposed.
// ---------------------------------------------------------------------------
__global__ __launch_bounds__(256) void proj3_mma(
    const float* __restrict__ xq, const float* __restrict__ xk,
    const float* __restrict__ xv,
    const float* __restrict__ Wq, const float* __restrict__ Wk,
    const float* __restrict__ Wv,
    const float* __restrict__ mq, const float* __restrict__ mk,
    const float* __restrict__ mv,
    __nv_bfloat16* __restrict__ qh, __nv_bfloat16* __restrict__ ql,
    __nv_bfloat16* __restrict__ kh, __nv_bfloat16* __restrict__ kl,
    __nv_bfloat16* __restrict__ vth, __nv_bfloat16* __restrict__ vtl)
{
    extern __shared__ char smem[];
    const uint32_t sb = smem_u32(smem);
    const uint32_t AH = 0, AL = 8192, BH = 16384, BL = 24576;
    const int tid = threadIdx.x, wid = tid >> 5, lane = tid & 31;
    const int m0 = blockIdx.x * 64;
    const int sel = blockIdx.y;

    const float* x    = sel == 0 ? xq : (sel == 1 ? xk : xv);
    const float* W    = sel == 0 ? Wq : (sel == 1 ? Wk : Wv);
    const float* mean = sel == 0 ? mq : (sel == 1 ? mk : mv);
    __nv_bfloat16* outh = sel == 0 ? qh : (sel == 1 ? kh : vth);
    __nv_bfloat16* outl = sel == 0 ? ql : (sel == 1 ? kl : vtl);
    const bool trans = (sel == 2);

    const int wm = wid >> 1, wn = wid & 1;
    const int mrow0 = wm * 16, ncol0 = wn * 32;
    float acc[4][4] = {};

    for (int k0 = 0; k0 < HIDDEN; k0 += 64) {
        #pragma unroll
        for (int i = tid; i < 1024; i += 256) {
            int r = i >> 4, c4 = i & 15;
            float4 xv4 = *(const float4*)&x[(size_t)(m0 + r) * HIDDEN + k0 + c4 * 4];
            float4 mn = *(const float4*)&mean[k0 + c4 * 4];
            uint32_t h0, l0, h1, l1;
            split2(xv4.x - mn.x, xv4.y - mn.y, h0, l0);
            split2(xv4.z - mn.z, xv4.w - mn.w, h1, l1);
            uint32_t so = sw128((uint32_t)r * 128 + c4 * 8);
            *(uint2*)(smem + AH + so) = make_uint2(h0, h1);
            *(uint2*)(smem + AL + so) = make_uint2(l0, l1);
        }
        #pragma unroll
        for (int i = tid; i < 1024; i += 256) {
            int r = i >> 4, c4 = i & 15;
            float4 wv = *(const float4*)&W[(size_t)r * HIDDEN + k0 + c4 * 4];
            uint32_t h0, l0, h1, l1;
            split2(wv.x, wv.y, h0, l0);
            split2(wv.z, wv.w, h1, l1);
            uint32_t so = sw128((uint32_t)r * 128 + c4 * 8);
            *(uint2*)(smem + BH + so) = make_uint2(h0, h1);
            *(uint2*)(smem + BL + so) = make_uint2(l0, l1);
        }
        __syncthreads();

        #pragma unroll
        for (int ks = 0; ks < 4; ks++) {
            uint32_t ah[4], al[4];
            uint32_t aa = a_addr(mrow0, ks, lane);
            ldm_x4(ah, sb + AH + aa);
            ldm_x4(al, sb + AL + aa);
            #pragma unroll
            for (int ntp = 0; ntp < 2; ntp++) {
                uint32_t bh[4], bl[4];
                uint32_t ba = b_addr(ncol0 + ntp * 16, ks, lane);
                ldm_x4(bh, sb + BH + ba);
                ldm_x4(bl, sb + BL + ba);
                mma_bf16(acc[ntp * 2 + 0], ah, &bh[0]);
                mma_bf16(acc[ntp * 2 + 0], al, &bh[0]);
                mma_bf16(acc[ntp * 2 + 0], ah, &bl[0]);
                mma_bf16(acc[ntp * 2 + 1], ah, &bh[2]);
                mma_bf16(acc[ntp * 2 + 1], al, &bh[2]);
                mma_bf16(acc[ntp * 2 + 1], ah, &bl[2]);
            }
        }
        __syncthreads();
    }

    #pragma unroll
    for (int nt = 0; nt < 4; nt++) {
        #pragma unroll
        for (int rh = 0; rh < 2; rh++) {
            int m = m0 + mrow0 + (lane >> 2) + rh * 8;
            int c = ncol0 + nt * 8 + (lane & 3) * 2;
            uint32_t hi, lo;
            split2(acc[nt][rh * 2 + 0], acc[nt][rh * 2 + 1], hi, lo);
            if (trans) {
                int b = m >> 12, s = m & 4095;
                size_t i0 = (size_t)b * KDIM * SKDIM + (size_t)c * SKDIM + s;
                size_t i1 = i0 + SKDIM;
                outh[i0] = __ushort_as_bfloat16((uint16_t)(hi & 0xffff));
                outh[i1] = __ushort_as_bfloat16((uint16_t)(hi >> 16));
                outl[i0] = __ushort_as_bfloat16((uint16_t)(lo & 0xffff));
                outl[i1] = __ushort_as_bfloat16((uint16_t)(lo >> 16));
            } else {
                *(uint32_t*)&outh[(size_t)m * KDIM + c] = hi;
                *(uint32_t*)&outl[(size_t)m * KDIM + c] = lo;
            }
        }
    }
}

// ---------------------------------------------------------------------------
// Pass 1: scores MMA -> raw scaled scores into attn region + softmax partials
// CTA tile 128q x 128s, 8 warps (4m x 2n), warp tile 32x64.
// ---------------------------------------------------------------------------
__global__ __launch_bounds__(256) void scores_mma(
    const __nv_bfloat16* __restrict__ qh, const __nv_bfloat16* __restrict__ ql,
    const __nv_bfloat16* __restrict__ kh, const __nv_bfloat16* __restrict__ kl,
    float* __restrict__ attn, float2* __restrict__ part)
{
    extern __shared__ char smem[];
    const uint32_t sb = smem_u32(smem);
    const uint32_t QH = 0, QL = 16384, KH = 32768, KL = 49152;
    const int tid = threadIdx.x, wid = tid >> 5, lane = tid & 31;
    const int b = blockIdx.z, q0 = blockIdx.y * 128, s0 = blockIdx.x * 128;

    const size_t qoff = ((size_t)b * SQDIM + q0) * KDIM;
    const size_t koff = ((size_t)b * SKDIM + s0) * KDIM;
    #pragma unroll
    for (int i = tid; i < 1024; i += 256) {
        int r = i >> 3, c = i & 7;
        uint32_t so = sw128((uint32_t)r * 128 + c * 16);
        *(uint4*)(smem + QH + so) = *(const uint4*)&qh[qoff + (size_t)r * KDIM + c * 8];
        *(uint4*)(smem + QL + so) = *(const uint4*)&ql[qoff + (size_t)r * KDIM + c * 8];
        *(uint4*)(smem + KH + so) = *(const uint4*)&kh[koff + (size_t)r * KDIM + c * 8];
        *(uint4*)(smem + KL + so) = *(const uint4*)&kl[koff + (size_t)r * KDIM + c * 8];
    }
    __syncthreads();

    const int wm = wid >> 1, wn = wid & 1;
    const int mrow0 = wm * 32, ncol0 = wn * 64;
    float acc[2][8][4] = {};

    #pragma unroll
    for (int ks = 0; ks < 4; ks++) {
        uint32_t ah[2][4], al[2][4];
        #pragma unroll
        for (int mt = 0; mt < 2; mt++) {
            uint32_t aa = a_addr(mrow0 + mt * 16, ks, lane);
            ldm_x4(ah[mt], sb + QH + aa);
            ldm_x4(al[mt], sb + QL + aa);
        }
        #pragma unroll
        for (int ntp = 0; ntp < 4; ntp++) {
            uint32_t bh[4], bl[4];
            uint32_t ba = b_addr(ncol0 + ntp * 16, ks, lane);
            ldm_x4(bh, sb + KH + ba);
            ldm_x4(bl, sb + KL + ba);
            #pragma unroll
            for (int mt = 0; mt < 2; mt++) {
                mma_bf16(acc[mt][ntp * 2 + 0], ah[mt], &bh[0]);
                mma_bf16(acc[mt][ntp * 2 + 0], al[mt], &bh[0]);
                mma_bf16(acc[mt][ntp * 2 + 0], ah[mt], &bl[0]);
                mma_bf16(acc[mt][ntp * 2 + 1], ah[mt], &bh[2]);
                mma_bf16(acc[mt][ntp * 2 + 1], al[mt], &bh[2]);
                mma_bf16(acc[mt][ntp * 2 + 1], ah[mt], &bl[2]);
            }
        }
    }

    const int stile = blockIdx.x * 2 + wn;
    #pragma unroll
    for (int mt = 0; mt < 2; mt++) {
        #pragma unroll
        for (int rh = 0; rh < 2; rh++) {
            int qrow = q0 + mrow0 + mt * 16 + (lane >> 2) + rh * 8;
            float* arow = attn + ((size_t)b * SQDIM + qrow) * SKDIM + s0 + ncol0;
            float v[16];
            float m = -3.4e38f;
            #pragma unroll
            for (int nt = 0; nt < 8; nt++) {
                v[nt * 2 + 0] = acc[mt][nt][rh * 2 + 0] * 0.125f;
                v[nt * 2 + 1] = acc[mt][nt][rh * 2 + 1] * 0.125f;
                m = fmaxf(m, fmaxf(v[nt * 2], v[nt * 2 + 1]));
                *(float2*)&arow[nt * 8 + (lane & 3) * 2] = make_float2(v[nt * 2], v[nt * 2 + 1]);
            }
            m = fmaxf(m, __shfl_xor_sync(0xffffffffu, m, 1));
            m = fmaxf(m, __shfl_xor_sync(0xffffffffu, m, 2));
            float s = 0.f;
            #pragma unroll
            for (int c = 0; c < 16; c++) s += __expf(v[c] - m);
            s += __shfl_xor_sync(0xffffffffu, s, 1);
            s += __shfl_xor_sync(0xffffffffu, s, 2);
            if ((lane & 3) == 0)
                part[((size_t)b * SQDIM + qrow) * 64 + stile] = make_float2(m, s);
        }
    }
}

// ---------------------------------------------------------------------------
// Combine 64 per-tile partials -> per-row (max, 1/sum). Warp per row.
// ---------------------------------------------------------------------------
__global__ __launch_bounds__(256) void rowstats_kernel(
    const float2* __restrict__ part, float2* __restrict__ rows)
{
    const int row = blockIdx.x * 8 + (threadIdx.x >> 5);
    const int lane = threadIdx.x & 31;
    float2 p0 = part[(size_t)row * 64 + lane];
    float2 p1 = part[(size_t)row * 64 + 32 + lane];
    float m = fmaxf(p0.x, p1.x);
    float s = p0.y * __expf(p0.x - m) + p1.y * __expf(p1.x - m);
    #pragma unroll
    for (int o = 16; o; o >>= 1) {
        float om = __shfl_xor_sync(0xffffffffu, m, o);
        float os = __shfl_xor_sync(0xffffffffu, s, o);
        float nm = fmaxf(m, om);
        s = s * __expf(m - nm) + os * __expf(om - nm);
        m = nm;
    }
    if (lane == 0) rows[row] = make_float2(m, 1.0f / s);
}

// ---------------------------------------------------------------------------
// Pass 2 (R14 optimum): normalize raw scores in place -> final attn, then
// p@V^T into split-K partials. CTA = 64q x 512s-split, 256 threads.
// V staged via cp.async; L2 prefetch of next score tile after the wait.
// smem: P0H 0 | P0L 8K | P1H 16K | P1L 24K | V0H 32K | V0L 40K |
//       V1H 48K | V1L 56K | RS 64K  (total ~64.5K)
// ---------------------------------------------------------------------------
__global__ __launch_bounds__(256) void av2_mma(
    float* __restrict__ attn,
    const __nv_bfloat16* __restrict__ vth, const __nv_bfloat16* __restrict__ vtl,
    const float2* __restrict__ rows, float* __restrict__ opart)
{
    extern __shared__ char smem[];
    const uint32_t sb = smem_u32(smem);
    const uint32_t P0H = 0, P0L = 8192, P1H = 16384, P1L = 24576;
    const uint32_t V0H = 32768, V0L = 40960, V1H = 49152, V1L = 57344;
    const uint32_t RS = 65536;
    const int tid = threadIdx.x, wid = tid >> 5, lane = tid & 31;
    const int qt = blockIdx.x, sp = blockIdx.y, b = blockIdx.z;
    const int q0 = qt * 64;

    if (tid < 64)
        *(float2*)(smem + RS + tid * 8) = rows[(size_t)b * SQDIM + q0 + tid];

    const __nv_bfloat16* vhb = vth + (size_t)b * KDIM * SKDIM;
    const __nv_bfloat16* vlb = vtl + (size_t)b * KDIM * SKDIM;
    float* attnb = attn + ((size_t)b * SQDIM + q0) * SKDIM;

    // normalize-loop addressing: 64 rows x 128 cols, 8 float4 per thread
    const int lrow = tid >> 5;           // 0..7
    const int lcol = lane * 4;           // 0..124
    const int halfsel = lcol >> 6;       // 0 or 1
    const int ch = lcol & 63;
    const uint32_t PHb = halfsel ? P1H : P0H;
    const uint32_t PLb = halfsel ? P1L : P0L;

    const int wm = wid >> 1, wn = wid & 1;
    const int mrow0 = wm * 16, ncol0 = wn * 32;
    float acc_av[4][4] = {};

    __syncthreads();  // RS visible

    for (int st = 0; st < SPLIT_S / 128; st++) {
        const int s0 = sp * SPLIT_S + st * 128;

        // V tiles via cp.async (overlap with normalize phase below)
        #pragma unroll
        for (int i = tid; i < 512; i += 256) {
            int j = i >> 3, c = i & 7;
            uint32_t so = sw128((uint32_t)j * 128 + c * 16);
            const size_t g0 = (size_t)j * SKDIM + s0 + c * 8;
            cp_async16(sb + V0H + so, &vhb[g0]);
            cp_async16(sb + V0L + so, &vlb[g0]);
            cp_async16(sb + V1H + so, &vhb[g0 + 64]);
            cp_async16(sb + V1L + so, &vlb[g0 + 64]);
        }
        cp_commit();

        // normalize: read raw scores, p = exp(s-m)*inv, write attn, stage smem
        #pragma unroll
        for (int it = 0; it < 8; it++) {
            int row = it * 8 + lrow;
            float* ap = attnb + (size_t)row * SKDIM + s0 + lcol;
            float4 x = *(const float4*)ap;
            float2 rs = *(const float2*)(smem + RS + row * 8);
            float4 p;
            p.x = __expf(x.x - rs.x) * rs.y;
            p.y = __expf(x.y - rs.x) * rs.y;
            p.z = __expf(x.z - rs.x) * rs.y;
            p.w = __expf(x.w - rs.x) * rs.y;
            *(float4*)ap = p;
            uint32_t h0, l0, h1, l1;
            split2(p.x, p.y, h0, l0);
            split2(p.z, p.w, h1, l1);
            uint32_t so = sw128((uint32_t)row * 128 + ch * 2);
            *(uint2*)(smem + PHb + so) = make_uint2(h0, h1);
            *(uint2*)(smem + PLb + so) = make_uint2(l0, l1);
        }
        cp_wait0();       // V(st) resident
        __syncthreads();

        // L2-prefetch next tile's scores (overlaps MMA below)
        if (st + 1 < SPLIT_S / 128) {
            const int sn = s0 + 128;
            #pragma unroll
            for (int it = 0; it < 8; it++) {
                int row = it * 8 + lrow;
                l2_prefetch(attnb + (size_t)row * SKDIM + sn + lcol);
            }
        }

        // AV: P(64x128) @ V^T(64x128) -> acc (64x64)
        #pragma unroll
        for (int half = 0; half < 2; half++) {
            const uint32_t PH = half ? P1H : P0H;
            const uint32_t PL = half ? P1L : P0L;
            const uint32_t VH = half ? V1H : V0H;
            const uint32_t VL = half ? V1L : V0L;
            #pragma unroll
            for (int ks = 0; ks < 4; ks++) {
                uint32_t ah[4], al[4];
                uint32_t aa = a_addr(mrow0, ks, lane);
                ldm_x4(ah, sb + PH + aa);
                ldm_x4(al, sb + PL + aa);
                #pragma unroll
                for (int ntp = 0; ntp < 2; ntp++) {
                    uint32_t bh[4], bl[4];
                    uint32_t ba = b_addr(ncol0 + ntp * 16, ks, lane);
                    ldm_x4(bh, sb + VH + ba);
                    ldm_x4(bl, sb + VL + ba);
                    mma_bf16(acc_av[ntp * 2 + 0], ah, &bh[0]);
                    mma_bf16(acc_av[ntp * 2 + 0], al, &bh[0]);
                    mma_bf16(acc_av[ntp * 2 + 0], ah, &bl[0]);
                    mma_bf16(acc_av[ntp * 2 + 1], ah, &bh[2]);
                    mma_bf16(acc_av[ntp * 2 + 1], al, &bh[2]);
                    mma_bf16(acc_av[ntp * 2 + 1], ah, &bl[2]);
                }
            }
        }
        __syncthreads();  // smem reuse next iteration
    }

    // write split-K partial
    float* op = opart + (size_t)sp * (BATCH * SQDIM * KDIM);
    #pragma unroll
    for (int nt = 0; nt < 4; nt++) {
        #pragma unroll
        for (int rh = 0; rh < 2; rh++) {
            int m = q0 + mrow0 + (lane >> 2) + rh * 8;
            int c = ncol0 + nt * 8 + (lane & 3) * 2;
            *(float2*)&op[((size_t)b * SQDIM + m) * KDIM + c] =
                make_float2(acc_av[nt][rh * 2 + 0], acc_av[nt][rh * 2 + 1]);
        }
    }
}

// ---------------------------------------------------------------------------
// Reduce split-K partials -> oc bf16 hi/lo
// ---------------------------------------------------------------------------
__global__ __launch_bounds__(256) void reduce_oc(
    const float* __restrict__ opart,
    __nv_bfloat16* __restrict__ och, __nv_bfloat16* __restrict__ ocl)
{
    const size_t i = ((size_t)blockIdx.x * 256 + threadIdx.x) * 2;
    const size_t STRIDE = (size_t)BATCH * SQDIM * KDIM;
    float a = 0.f, c = 0.f;
    #pragma unroll
    for (int s = 0; s < NSPLIT; s++) {
        float2 v = *(const float2*)&opart[s * STRIDE + i];
        a += v.x;
        c += v.y;
    }
    uint32_t hi, lo;
    split2(a, c, hi, lo);
    *(uint32_t*)&och[i] = hi;
    *(uint32_t*)&ocl[i] = lo;
}

// ---------------------------------------------------------------------------
// Out-proj (mma.sync): out[m][h] = oc[m] . W_out[h] + bias[h]
// CTA 128m x 128h, K = 64. 8 warps (4m x 2n), warp 32x64.
// ---------------------------------------------------------------------------
__global__ __launch_bounds__(256) void oproj_mma(
    const __nv_bfloat16* __restrict__ och, const __nv_bfloat16* __restrict__ ocl,
    const float* __restrict__ W, const float* __restrict__ bias,
    float* __restrict__ out)
{
    extern __shared__ char smem[];
    const uint32_t sb = smem_u32(smem);
    const uint32_t AH = 0, AL = 16384, BH = 32768, BL = 49152;
    const int tid = threadIdx.x, wid = tid >> 5, lane = tid & 31;
    const int m0 = blockIdx.y * 128, n0 = blockIdx.x * 128;

    #pragma unroll
    for (int i = tid; i < 1024; i += 256) {
        int r = i >> 3, c = i & 7;
        uint32_t so = sw128((uint32_t)r * 128 + c * 16);
        *(uint4*)(smem + AH + so) = *(const uint4*)&och[(size_t)(m0 + r) * KDIM + c * 8];
        *(uint4*)(smem + AL + so) = *(const uint4*)&ocl[(size_t)(m0 + r) * KDIM + c * 8];
    }
    #pragma unroll 2
    for (int i = tid; i < 2048; i += 256) {
        int r = i >> 4, c4 = i & 15;
        float4 wv = *(const float4*)&W[(size_t)(n0 + r) * KDIM + c4 * 4];
        uint32_t h0, l0, h1, l1;
        split2(wv.x, wv.y, h0, l0);
        split2(wv.z, wv.w, h1, l1);
        uint32_t so = sw128((uint32_t)r * 128 + c4 * 8);
        *(uint2*)(smem + BH + so) = make_uint2(h0, h1);
        *(uint2*)(smem + BL + so) = make_uint2(l0, l1);
    }
    __syncthreads();

    const int wm = wid >> 1, wn = wid & 1;
    const int mrow0 = wm * 32, ncol0 = wn * 64;
    float acc[2][8][4] = {};

    #pragma unroll
    for (int ks = 0; ks < 4; ks++) {
        uint32_t ah[2][4], al[2][4];
        #pragma unroll
        for (int mt = 0; mt < 2; mt++) {
            uint32_t aa = a_addr(mrow0 + mt * 16, ks, lane);
            ldm_x4(ah[mt], sb + AH + aa);
            ldm_x4(al[mt], sb + AL + aa);
        }
        #pragma unroll
        for (int ntp = 0; ntp < 4; ntp++) {
            uint32_t bh[4], bl[4];
            uint32_t ba = b_addr(ncol0 + ntp * 16, ks, lane);
            ldm_x4(bh, sb + BH + ba);
            ldm_x4(bl, sb + BL + ba);
            #pragma unroll
            for (int mt = 0; mt < 2; mt++) {
                mma_bf16(acc[mt][ntp * 2 + 0], ah[mt], &bh[0]);
                mma_bf16(acc[mt][ntp * 2 + 0], al[mt], &bh[0]);
                mma_bf16(acc[mt][ntp * 2 + 0], ah[mt], &bl[0]);
                mma_bf16(acc[mt][ntp * 2 + 1], ah[mt], &bh[2]);
                mma_bf16(acc[mt][ntp * 2 + 1], al[mt], &bh[2]);
                mma_bf16(acc[mt][ntp * 2 + 1], ah[mt], &bl[2]);
            }
        }
    }

    #pragma unroll
    for (int mt = 0; mt < 2; mt++) {
        #pragma unroll
        for (int nt = 0; nt < 8; nt++) {
            #pragma unroll
            for (int rh = 0; rh < 2; rh++) {
                int m = m0 + mrow0 + mt * 16 + (lane >> 2) + rh * 8;
                int h = n0 + ncol0 + nt * 8 + (lane & 3) * 2;
                float2 o;
                o.x = acc[mt][nt][rh * 2 + 0] + bias[h];
                o.y = acc[mt][nt][rh * 2 + 1] + bias[h + 1];
                *(float2*)&out[(size_t)m * HIDDEN + h] = o;
            }
        }
    }
}

// ---------------------------------------------------------------------------
extern "C" void kernel_launch(void* const* d_in, const int* in_sizes, int n_in,
                              void* d_out, int out_size)
{
    const float* query  = (const float*)d_in[0];
    const float* key    = (const float*)d_in[1];
    const float* value  = (const float*)d_in[2];
    const float* Wq     = (const float*)d_in[3];
    const float* Wk     = (const float*)d_in[4];
    const float* Wv     = (const float*)d_in[5];
    const float* q_mean = (const float*)d_in[6];
    const float* k_mean = (const float*)d_in[7];
    const float* v_mean = (const float*)d_in[8];
    const float* W_out  = (const float*)d_in[9];
    const float* b_out  = (const float*)d_in[10];

    float* out_ptr  = (float*)d_out;
    float* attn_ptr = (float*)d_out + (size_t)BATCH * SQDIM * HIDDEN;

    __nv_bfloat16 *qh, *ql, *kh, *kl, *vth, *vtl, *och, *ocl;
    float *opart;
    float2 *part, *rows;
    cudaGetSymbolAddress((void**)&qh, g_qh);
    cudaGetSymbolAddress((void**)&ql, g_ql);
    cudaGetSymbolAddress((void**)&kh, g_kh);
    cudaGetSymbolAddress((void**)&kl, g_kl);
    cudaGetSymbolAddress((void**)&vth, g_vth);
    cudaGetSymbolAddress((void**)&vtl, g_vtl);
    cudaGetSymbolAddress((void**)&och, g_och);
    cudaGetSymbolAddress((void**)&ocl, g_ocl);
    cudaGetSymbolAddress((void**)&opart, g_opart);
    cudaGetSymbolAddress((void**)&part, g_part);
    cudaGetSymbolAddress((void**)&rows, g_rows);

    cudaFuncSetAttribute(proj3_mma, cudaFuncAttributeMaxDynamicSharedMemorySize, 32768);
    cudaFuncSetAttribute(scores_mma, cudaFuncAttributeMaxDynamicSharedMemorySize, 65536);
    cudaFuncSetAttribute(av2_mma, cudaFuncAttributeMaxDynamicSharedMemorySize, 66048);
    cudaFuncSetAttribute(oproj_mma, cudaFuncAttributeMaxDynamicSharedMemorySize, 65536);

    const int Mrows = BATCH * SQDIM;  // 16384

    dim3 pg(Mrows / 64, 3);
    proj3_mma<<<pg, 256, 32768>>>(query, key, value, Wq, Wk, Wv,
                                  q_mean, k_mean, v_mean,
                                  qh, ql, kh, kl, vth, vtl);

    dim3 sg(SKDIM / 128, SQDIM / 128, BATCH);
    scores_mma<<<sg, 256, 65536>>>(qh, ql, kh, kl, attn_ptr, part);

    rowstats_kernel<<<Mrows / 8, 256>>>(part, rows);

    dim3 fg(SQDIM / 64, NSPLIT, BATCH);
    av2_mma<<<fg, 256, 66048>>>(attn_ptr, vth, vtl, rows, opart);

    reduce_oc<<<(Mrows * KDIM / 2) / 256, 256>>>(opart, och, ocl);

    dim3 og(HIDDEN / 128, Mrows / 128);
    oproj_mma<<<og, 256, 65536>>>(och, ocl, W_out, b_out, out_ptr);
}